// round 16
// baseline (speedup 1.0000x reference)
#include <cuda_runtime.h>
#include <cuda_fp16.h>
#include <stdint.h>
#include <math.h>

// Problem constants
#define TT   512
#define BB   64
#define INN  512
#define HH   1024
#define G4   4096   // 4*HH

#define NCTAP  128     // persistent CTAs; CTA j owns units [8j, 8j+8), all 4 gates => M=32 rows
#define NCHUNK 8       // K chunks of 128
#define NSTAGE 4
#define NGRP   8       // chunk groups (= NCHUNK); group c produced by CTAs 16c..16c+15

// ---------------- persistent-kernel smem layout (bytes) ----------------
#define WPITCH 2064                      // 1024 fp16 = 2048B payload + 16B rotation
#define SM_W    0
#define SM_H    66048                    // 32*2064
#define HPITCH  272                      // 128 fp16 = 256B payload + 16B rotation
#define HSTG    17408                    // 64 rows * 272
#define SM_XP   135680                   // 66048 + 4*17408
#define SM_FLG  143872                   // 8 int flags (chunk-group readiness)
#define SMEM_REQ 143904

// ---------------- xproj mma kernel smem ----------------
#define XPA     0
#define XPB     18432                    // 128 rows * 144
#define XPSTG   36864
#define XP_SMEM (4 * XPSTG)              // 147456

// ---------------- device scratch (allocation-free rule) ----------------
__device__ float g_xproj[(size_t)TT * BB * G4];                     // [T*B][4H] fp32
__device__ __align__(16) unsigned char g_xh[(size_t)TT * BB * INN * 2];      // xs fp16 [m][k] 32MB
__device__ __align__(16) unsigned char g_wih[(size_t)G4 * INN * 2];          // W_ih fp16 [n][k] 4MB
__device__ __align__(16) unsigned char g_whh[(size_t)NCTAP * 32 * HH * 2];   // W_hh fp16 tiles 8MB
__device__ __align__(16) unsigned char g_hb[2][BB * HH * 2];        // h fp16 [b][k], ping-pong
__device__ unsigned g_ready[(TT + 1) * NGRP];                       // per-(step,group) arrivals; 16 = ready

// ---------------- helpers ----------------
__device__ __forceinline__ uint32_t smem_u32(const void* p) {
    uint32_t a;
    asm("{ .reg .u64 t; cvta.to.shared.u64 t, %1; cvt.u32.u64 %0, t; }" : "=r"(a) : "l"(p));
    return a;
}

__device__ __forceinline__ uint4 pack8h(float4 a, float4 b) {
    __half2 p0 = __floats2half2_rn(a.x, a.y);
    __half2 p1 = __floats2half2_rn(a.z, a.w);
    __half2 p2 = __floats2half2_rn(b.x, b.y);
    __half2 p3 = __floats2half2_rn(b.z, b.w);
    return make_uint4(*(uint32_t*)&p0, *(uint32_t*)&p1, *(uint32_t*)&p2, *(uint32_t*)&p3);
}

__device__ __forceinline__ float fsig(float x)  { return __fdividef(1.0f, 1.0f + __expf(-x)); }
__device__ __forceinline__ float ftanh(float x) { return 1.0f - __fdividef(2.0f, __expf(2.0f * x) + 1.0f); }

// ---------------- PTX wrappers (baseline compute_103 features only) ----------------
__device__ __forceinline__ void cpasync16(uint32_t dst, const void* src) {
    asm volatile("cp.async.cg.shared.global [%0], [%1], 16;" :: "r"(dst), "l"(src) : "memory");
}
#define CP_COMMIT() asm volatile("cp.async.commit_group;" ::: "memory")
#define CP_WAIT2()  asm volatile("cp.async.wait_group 2;" ::: "memory")
#define CP_WAIT0()  asm volatile("cp.async.wait_group 0;" ::: "memory")

// named barrier for the 8 worker warps (poller warp never joins)
#define WBAR() asm volatile("bar.sync 1, 256;" ::: "memory")

__device__ __forceinline__ void ldm4(uint32_t* r, uint32_t addr) {
    asm volatile("ldmatrix.sync.aligned.m8n8.x4.shared.b16 {%0,%1,%2,%3}, [%4];"
        : "=r"(r[0]), "=r"(r[1]), "=r"(r[2]), "=r"(r[3]) : "r"(addr));
}
__device__ __forceinline__ void mma16816h(float* d, const uint32_t* a, uint32_t b0, uint32_t b1) {
    asm volatile(
        "mma.sync.aligned.m16n8k16.row.col.f32.f16.f16.f32 "
        "{%0,%1,%2,%3}, {%4,%5,%6,%7}, {%8,%9}, {%0,%1,%2,%3};"
        : "+f"(d[0]), "+f"(d[1]), "+f"(d[2]), "+f"(d[3])
        : "r"(a[0]), "r"(a[1]), "r"(a[2]), "r"(a[3]), "r"(b0), "r"(b1));
}

__device__ __forceinline__ unsigned ldrelax(const unsigned* p) {
    unsigned v;
    asm volatile("ld.relaxed.gpu.global.u32 %0, [%1];" : "=r"(v) : "l"(p) : "memory");
    return v;
}

// worker-side: wait until smem flag for group c reaches step t (steady state: 1 LDS)
__device__ __forceinline__ void wait_grp(uint32_t sa, int t) {
    int v;
    do {
        asm volatile("ld.acquire.cta.shared.b32 %0, [%1];" : "=r"(v) : "r"(sa) : "memory");
    } while (v < t);
}

// ---------------------------------------------------------------------------
// Prep kernels: fp32 -> fp16 conversions.
// ---------------------------------------------------------------------------
__global__ __launch_bounds__(256)
void prep_xh_kernel(const float* __restrict__ xs)
{
    size_t idx = (size_t)blockIdx.x * 256 + threadIdx.x;
    const float* s = xs + idx * 8;
    float4 a = *(const float4*)s;
    float4 b = *(const float4*)(s + 4);
    *(uint4*)(g_xh + idx * 16) = pack8h(a, b);
}

__global__ __launch_bounds__(256)
void prep_wih_kernel(const float* __restrict__ Wih)
{
    size_t idx = (size_t)blockIdx.x * 256 + threadIdx.x;
    const float* s = Wih + idx * 8;
    float4 a = *(const float4*)s;
    float4 b = *(const float4*)(s + 4);
    *(uint4*)(g_wih + idx * 16) = pack8h(a, b);
}

__global__ __launch_bounds__(256)
void prep_whh_kernel(const float* __restrict__ Whh)
{
    int idx = blockIdx.x * 256 + threadIdx.x;
    int kg = idx & 127;
    int r  = (idx >> 7) & 31;
    int j  = idx >> 12;

    int gate = r >> 3;
    int u    = 8 * j + (r & 7);
    const float* src = Whh + ((size_t)(gate * HH + u)) * HH + kg * 8;
    float4 a = *(const float4*)src;
    float4 b = *(const float4*)(src + 4);

    size_t off = ((size_t)(j * 32 + r) * HH + (size_t)kg * 8) * 2;
    *(uint4*)(g_whh + off) = pack8h(a, b);
}

__global__ __launch_bounds__(256)
void init_h_kernel(const float* __restrict__ h0)
{
    int idx = blockIdx.x * 256 + threadIdx.x;
    const float* src = h0 + (size_t)idx * 8;
    float4 a = *(const float4*)src;
    float4 b = *(const float4*)(src + 4);
    *(uint4*)(g_hb[0] + (size_t)idx * 16) = pack8h(a, b);
}

__global__ __launch_bounds__(256)
void reset_flags_kernel()
{
    int idx = blockIdx.x * 256 + threadIdx.x;
    if (idx < (TT + 1) * NGRP) g_ready[idx] = (idx < NGRP) ? 16u : 0u;
}

// ---------------------------------------------------------------------------
// xproj GEMM on tensor cores (fp16): g_xproj = xs*Wih^T + bias.  (unchanged)
// ---------------------------------------------------------------------------
__device__ __forceinline__ void xp_load_stage(uint32_t smb, int s, int c,
                                              int mbase, int nbase, int tid)
{
    uint32_t stg = smb + (uint32_t)s * XPSTG;
#pragma unroll
    for (int n = 0; n < 4; n++) {
        int i = tid + n * 256;
        int row = i >> 3;
        int col = i & 7;
        uint32_t d = (uint32_t)row * 144 + (uint32_t)col * 16;
        cpasync16(stg + XPA + d,
                  g_xh + ((size_t)(mbase + row) * INN + (size_t)c * 64 + col * 8) * 2);
        cpasync16(stg + XPB + d,
                  g_wih + ((size_t)(nbase + row) * INN + (size_t)c * 64 + col * 8) * 2);
    }
}

__global__ __launch_bounds__(256, 1)
void xprojmma_kernel(const float* __restrict__ bih, const float* __restrict__ bhh)
{
    extern __shared__ char sm[];
    uint32_t smb = smem_u32(sm);

    const int tid  = threadIdx.x;
    const int wid  = tid >> 5;
    const int lane = tid & 31;
    const int nbase = blockIdx.x * 128;
    const int mbase = blockIdx.y * 128;

    const int m0 = (wid & 1) * 64;
    const int n0 = (wid >> 1) * 32;

    const int mat = lane >> 3;
    const uint32_t arow = (uint32_t)((lane & 7) + ((mat & 1) << 3));
    const uint32_t acol = (uint32_t)(mat >> 1) * 16;
    const uint32_t brow = (uint32_t)((lane & 7) + ((mat >> 1) << 3));
    const uint32_t bcol = (uint32_t)(mat & 1) * 16;

    float acc[4][4][4];
#pragma unroll
    for (int im = 0; im < 4; im++)
#pragma unroll
        for (int in = 0; in < 4; in++)
#pragma unroll
            for (int k = 0; k < 4; k++) acc[im][in][k] = 0.0f;

#pragma unroll
    for (int c = 0; c < 3; c++) { xp_load_stage(smb, c, c, mbase, nbase, tid); CP_COMMIT(); }

    for (int c = 0; c < 8; c++) {
        CP_WAIT2();
        __syncthreads();
        if (c + 3 < 8) xp_load_stage(smb, (c + 3) & 3, c + 3, mbase, nbase, tid);
        CP_COMMIT();

        const uint32_t stg = smb + (uint32_t)(c & 3) * XPSTG;
#pragma unroll
        for (int ks = 0; ks < 4; ks++) {
            const uint32_t kb = (uint32_t)ks * 32;
            uint32_t a[4][4], b0[4], b1[4];
#pragma unroll
            for (int im = 0; im < 4; im++)
                ldm4(a[im], stg + XPA + (uint32_t)(m0 + im * 16 + arow) * 144 + acol + kb);
            ldm4(b0, stg + XPB + (uint32_t)(n0 + brow) * 144 + bcol + kb);
            ldm4(b1, stg + XPB + (uint32_t)(n0 + 16 + brow) * 144 + bcol + kb);
#pragma unroll
            for (int im = 0; im < 4; im++) {
                mma16816h(acc[im][0], a[im], b0[0], b0[1]);
                mma16816h(acc[im][1], a[im], b0[2], b0[3]);
                mma16816h(acc[im][2], a[im], b1[0], b1[1]);
                mma16816h(acc[im][3], a[im], b1[2], b1[3]);
            }
        }
    }

    const int crow  = lane >> 2;
    const int ccol2 = (lane & 3) * 2;
#pragma unroll
    for (int in = 0; in < 4; in++) {
        const int gcol = nbase + n0 + in * 8 + ccol2;
        float bx = bih[gcol]     + bhh[gcol];
        float by = bih[gcol + 1] + bhh[gcol + 1];
#pragma unroll
        for (int im = 0; im < 4; im++) {
            const int r0 = mbase + m0 + im * 16 + crow;
            float2 v0 = make_float2(acc[im][in][0] + bx, acc[im][in][1] + by);
            float2 v1 = make_float2(acc[im][in][2] + bx, acc[im][in][3] + by);
            *(float2*)(g_xproj + (size_t)r0 * G4 + gcol)       = v0;
            *(float2*)(g_xproj + (size_t)(r0 + 8) * G4 + gcol) = v1;
        }
    }
}

// ---------------------------------------------------------------------------
// Persistent LSTM kernel, warp-specialized dataflow sync:
// 128 CTAs x 288 threads (8 worker warps + 1 poller warp).
// Chunk group c of h_{t+1} is produced by CTAs 16c..16c+15; g_ready counts
// arrivals (16 = ready). ONE poller thread per CTA batch-polls the 8 flags
// (relaxed, MLP-parallel) and publishes readiness into smem; the 8 worker
// warps gate chunk loads on cheap smem acquire-loads. No full-grid barrier.
// ---------------------------------------------------------------------------
__device__ __forceinline__ void load_h_chunk(uint32_t smb, int s, int c, int tid,
                                             const unsigned char* hbase)
{
    uint32_t stg = smb + SM_H + (uint32_t)s * HSTG;
#pragma unroll
    for (int n = 0; n < 4; n++) {
        int i = tid + n * 256;            // 0..1023 (16B segs)
        int row = i >> 4;                 // batch 0..63
        int col = i & 15;                 // 16B col within 256B
        uint32_t d = (uint32_t)row * HPITCH + (uint32_t)col * 16;
        size_t sg = (size_t)row * 2048 + (size_t)c * 256 + (size_t)col * 16;
        cpasync16(stg + d, hbase + sg);
    }
}

__global__ __launch_bounds__(288, 1)
void persist_kernel(const float* __restrict__ c0, float* __restrict__ out)
{
    extern __shared__ char sm[];
    uint32_t smb = smem_u32(sm);

    const int tid  = threadIdx.x;
    const int j    = blockIdx.x;
    const int n0   = j * 8;
    const uint32_t FLG = smb + SM_FLG;

    // ---- init smem flags (one worker thread), then full 288-thread sync ----
    if (tid == 0) {
#pragma unroll
        for (int c = 0; c < NGRP; c++) ((int*)(sm + SM_FLG))[c] = -1;
    }

    // ---- workers issue W-tile loads before the full sync ----
    if (tid < 256) {
        const unsigned char* wh = g_whh + (size_t)j * 65536;
#pragma unroll
        for (int n = 0; n < 16; n++) {
            int e = n * 256 + tid;
            uint32_t d = (uint32_t)(e >> 7) * WPITCH + (uint32_t)(e & 127) * 16;
            cpasync16(smb + SM_W + d, wh + (size_t)e * 16);
        }
        CP_COMMIT();
        CP_WAIT0();
    }
    __syncthreads();   // ALL 288 threads: flags init + W tile visible

    // ================= poller warp =================
    if (tid >= 256) {
        if (tid == 256) {
            for (int t = 0; t < TT; t++) {
                const unsigned* fl = g_ready + (size_t)t * NGRP;
                unsigned got = 0;
                while (got != 0xFFu) {
                    unsigned v[NGRP];
#pragma unroll
                    for (int c = 0; c < NGRP; c++)
                        v[c] = ((got >> c) & 1u) ? 16u : ldrelax(fl + c);
                    unsigned newly = 0;
#pragma unroll
                    for (int c = 0; c < NGRP; c++)
                        if (!((got >> c) & 1u) && v[c] >= 16u) newly |= 1u << c;
                    if (newly) {
                        asm volatile("fence.acq_rel.gpu;" ::: "memory");
#pragma unroll
                        for (int c = 0; c < NGRP; c++)
                            if ((newly >> c) & 1u)
                                asm volatile("st.release.cta.shared.b32 [%0], %1;"
                                             :: "r"(FLG + c * 4), "r"(t) : "memory");
                        got |= newly;
                    }
                }
            }
        }
        return;
    }

    // ================= worker warps (tid < 256) =================
    const int wid  = tid >> 5;
    const int lane = tid & 31;
    const int m0  = (wid & 1) * 16;
    const int bn0 = (wid >> 1) * 16;

    const int mat = lane >> 3;
    const uint32_t aW   = (uint32_t)(m0 + (lane & 7) + ((mat & 1) << 3)) * WPITCH
                        + (uint32_t)(mat >> 1) * 16;
    const uint32_t boff = (uint32_t)(bn0 + (lane & 7) + ((mat >> 1) << 3)) * HPITCH
                        + (uint32_t)(mat & 1) * 16;

    const int eb  = tid >> 2;
    const int eup = (tid & 3) * 2;
    float2 creg = *(const float2*)(c0 + (size_t)eb * HH + n0 + eup);

    float* gs = (float*)(sm + SM_H);          // gate exchange overlay (stage 0)
    const float* xpb = (const float*)(sm + SM_XP);

    for (int t = 0; t < TT; t++) {
        const unsigned char* hread = g_hb[t & 1];
        unsigned char* hwrite      = g_hb[(t & 1) ^ 1];

        // ---- prologue: chunks 0..2 (+ xproj tile in group 0) ----
        wait_grp(FLG + 0 * 4, t);
        load_h_chunk(smb, 0, 0, tid, hread);
        {
#pragma unroll
            for (int n = 0; n < 2; n++) {
                int i = tid * 2 + n;
                int half = i & 1;
                int g = (i >> 1) & 3;
                int b = i >> 3;
                const float* src = g_xproj + ((size_t)t * BB + b) * G4
                                 + (size_t)g * HH + n0 + half * 4;
                cpasync16(smb + SM_XP + (uint32_t)b * 128 + (uint32_t)g * 32
                          + (uint32_t)half * 16, src);
            }
        }
        CP_COMMIT();
        wait_grp(FLG + 1 * 4, t);
        load_h_chunk(smb, 1, 1, tid, hread);
        CP_COMMIT();
        wait_grp(FLG + 2 * 4, t);
        load_h_chunk(smb, 2, 2, tid, hread);
        CP_COMMIT();

        float acc[2][4];
#pragma unroll
        for (int i = 0; i < 2; i++)
#pragma unroll
            for (int k = 0; k < 4; k++) acc[i][k] = 0.0f;

        // ---- 8 K-chunks of 128, 4-stage pipeline ----
        for (int c = 0; c < NCHUNK; c++) {
            CP_WAIT2();
            WBAR();
            if (c + 3 < NCHUNK) {
                wait_grp(FLG + (c + 3) * 4, t);
                load_h_chunk(smb, (c + 3) & 3, c + 3, tid, hread);
            }
            CP_COMMIT();

            const uint32_t stg = smb + SM_H + (uint32_t)(c & 3) * HSTG;
            const uint32_t wcol = (uint32_t)c * 256;
#pragma unroll
            for (int ks = 0; ks < 8; ks++) {
                const uint32_t kb = (uint32_t)ks * 32;
                uint32_t ah[4], bh[4];
                ldm4(ah, smb + SM_W + aW + wcol + kb);
                ldm4(bh, stg + boff + kb);
                mma16816h(acc[0], ah, bh[0], bh[1]);
                mma16816h(acc[1], ah, bh[2], bh[3]);
            }
        }
        // no barrier: gate exchange writes stage 0, last read at chunk 4,
        // separated by in-loop WBARs at c=5..7.

        // ---- gate exchange: fragments -> gs[32][68] ----
        {
            const int row0 = m0 + (lane >> 2);
            const int col0 = bn0 + (lane & 3) * 2;
            gs[row0 * 68 + col0]           = acc[0][0];
            gs[row0 * 68 + col0 + 1]       = acc[0][1];
            gs[(row0 + 8) * 68 + col0]     = acc[0][2];
            gs[(row0 + 8) * 68 + col0 + 1] = acc[0][3];
            gs[row0 * 68 + col0 + 8]       = acc[1][0];
            gs[row0 * 68 + col0 + 9]       = acc[1][1];
            gs[(row0 + 8) * 68 + col0 + 8] = acc[1][2];
            gs[(row0 + 8) * 68 + col0 + 9] = acc[1][3];
        }
        WBAR();

        // ---- fused epilogue (fast-math): (b, 2 units) per thread ----
        {
            float hv0, hv1;
            {
                const int u = eup;
                float gi = gs[(u)      * 68 + eb] + xpb[eb * 32 + 0 * 8 + u];
                float gf = gs[(8 + u)  * 68 + eb] + xpb[eb * 32 + 1 * 8 + u];
                float gg = gs[(16 + u) * 68 + eb] + xpb[eb * 32 + 2 * 8 + u];
                float go = gs[(24 + u) * 68 + eb] + xpb[eb * 32 + 3 * 8 + u];
                float ii = fsig(gi), ff = fsig(gf), gt = ftanh(gg), oo = fsig(go);
                float cn = ff * creg.x + ii * gt;
                creg.x = cn;
                hv0 = oo * ftanh(cn);
            }
            {
                const int u = eup + 1;
                float gi = gs[(u)      * 68 + eb] + xpb[eb * 32 + 0 * 8 + u];
                float gf = gs[(8 + u)  * 68 + eb] + xpb[eb * 32 + 1 * 8 + u];
                float gg = gs[(16 + u) * 68 + eb] + xpb[eb * 32 + 2 * 8 + u];
                float go = gs[(24 + u) * 68 + eb] + xpb[eb * 32 + 3 * 8 + u];
                float ii = fsig(gi), ff = fsig(gf), gt = ftanh(gg), oo = fsig(go);
                float cn = ff * creg.y + ii * gt;
                creg.y = cn;
                hv1 = oo * ftanh(cn);
            }

            // h blob first (inter-CTA critical path), then out
            __half2 hp = __floats2half2_rn(hv0, hv1);
            *(uint32_t*)(hwrite + (size_t)eb * 2048 + (size_t)(n0 + eup) * 2)
                = *(uint32_t*)&hp;

            *(float2*)(out + ((size_t)t * BB + eb) * HH + n0 + eup) = make_float2(hv0, hv1);
        }
        WBAR();   // all hwrite stores done CTA-wide; also protects gs reuse

        // ---- producer arrival only; no wait (poller + smem flags gate reads) ----
        if (tid == 0) {
            __threadfence();
            asm volatile("red.relaxed.gpu.global.add.u32 [%0], %1;"
                         :: "l"(&g_ready[(t + 1) * NGRP + (j >> 4)]), "r"(1u) : "memory");
        }
    }
}

// ---------------------------------------------------------------------------
// Launch
// ---------------------------------------------------------------------------
extern "C" void kernel_launch(void* const* d_in, const int* in_sizes, int n_in,
                              void* d_out, int out_size)
{
    const float* xs  = (const float*)d_in[0];   // [T,B,IN]
    const float* h0  = (const float*)d_in[1];   // [B,H]
    const float* c0  = (const float*)d_in[2];   // [B,H]
    const float* Wih = (const float*)d_in[3];   // [4H,IN]
    const float* Whh = (const float*)d_in[4];   // [4H,H]
    const float* bih = (const float*)d_in[5];   // [4H]
    const float* bhh = (const float*)d_in[6];   // [4H]
    float* out = (float*)d_out;                 // [T,B,H]

    (void)in_sizes; (void)n_in; (void)out_size;

    cudaFuncSetAttribute(persist_kernel,  cudaFuncAttributeMaxDynamicSharedMemorySize, SMEM_REQ);
    cudaFuncSetAttribute(xprojmma_kernel, cudaFuncAttributeMaxDynamicSharedMemorySize, XP_SMEM);

    prep_xh_kernel<<<8192, 256>>>(xs);
    prep_wih_kernel<<<1024, 256>>>(Wih);
    prep_whh_kernel<<<2048, 256>>>(Whh);
    init_h_kernel<<<32, 256>>>(h0);
    reset_flags_kernel<<<17, 256>>>();

    xprojmma_kernel<<<dim3(32, 256), 256, XP_SMEM>>>(bih, bhh);

    persist_kernel<<<NCTAP, 288, SMEM_REQ>>>(c0, out);
}

// round 17
// speedup vs baseline: 1.2045x; 1.2045x over previous
#include <cuda_runtime.h>
#include <cuda_fp16.h>
#include <stdint.h>
#include <math.h>

// Problem constants
#define TT   512
#define BB   64
#define INN  512
#define HH   1024
#define G4   4096   // 4*HH

#define NCTAP  128     // persistent CTAs; CTA j owns units [8j, 8j+8), all 4 gates => M=32 rows
#define NCHUNK 8       // K chunks of 128
#define NSTAGE 4

// ---------------- persistent-kernel smem layout (bytes) ----------------
#define WPITCH 2064                      // 1024 fp16 = 2048B payload + 16B rotation
#define SM_W    0
#define SM_H    66048                    // 32*2064
#define HPITCH  272                      // 128 fp16 = 256B payload + 16B rotation
#define HSTG    17408                    // 64 rows * 272
#define SM_XP   135680                   // 66048 + 4*17408
#define SMEM_REQ 143872                  // + 8192 xproj tile

// ---------------- xproj mma kernel smem ----------------
#define XPA     0
#define XPB     18432                    // 128 rows * 144
#define XPSTG   36864
#define XP_SMEM (4 * XPSTG)              // 147456

// ---------------- device scratch (allocation-free rule) ----------------
__device__ float g_xproj[(size_t)TT * BB * G4];                     // [T*B][4H] fp32
__device__ __align__(16) unsigned char g_xh[(size_t)TT * BB * INN * 2];      // xs fp16 [m][k] 32MB
__device__ __align__(16) unsigned char g_wih[(size_t)G4 * INN * 2];          // W_ih fp16 [n][k] 4MB
__device__ __align__(16) unsigned char g_whh[(size_t)NCTAP * 32 * HH * 2];   // W_hh fp16 tiles 8MB
__device__ __align__(16) unsigned char g_hb[2][BB * HH * 2];        // h fp16 [b][k], ping-pong
__device__ unsigned g_cnt;                                          // monotonic barrier counter

// ---------------- helpers ----------------
__device__ __forceinline__ uint32_t smem_u32(const void* p) {
    uint32_t a;
    asm("{ .reg .u64 t; cvta.to.shared.u64 t, %1; cvt.u32.u64 %0, t; }" : "=r"(a) : "l"(p));
    return a;
}

__device__ __forceinline__ uint4 pack8h(float4 a, float4 b) {
    __half2 p0 = __floats2half2_rn(a.x, a.y);
    __half2 p1 = __floats2half2_rn(a.z, a.w);
    __half2 p2 = __floats2half2_rn(b.x, b.y);
    __half2 p3 = __floats2half2_rn(b.z, b.w);
    return make_uint4(*(uint32_t*)&p0, *(uint32_t*)&p1, *(uint32_t*)&p2, *(uint32_t*)&p3);
}

__device__ __forceinline__ float fsig(float x)  { return __fdividef(1.0f, 1.0f + __expf(-x)); }
__device__ __forceinline__ float ftanh(float x) { return 1.0f - __fdividef(2.0f, __expf(2.0f * x) + 1.0f); }

// ---------------- PTX wrappers (baseline compute_103 features only) ----------------
__device__ __forceinline__ void cpasync16(uint32_t dst, const void* src) {
    asm volatile("cp.async.cg.shared.global [%0], [%1], 16;" :: "r"(dst), "l"(src) : "memory");
}
#define CP_COMMIT() asm volatile("cp.async.commit_group;" ::: "memory")
#define CP_WAIT2()  asm volatile("cp.async.wait_group 2;" ::: "memory")
#define CP_WAIT0()  asm volatile("cp.async.wait_group 0;" ::: "memory")

__device__ __forceinline__ void ldm4(uint32_t* r, uint32_t addr) {
    asm volatile("ldmatrix.sync.aligned.m8n8.x4.shared.b16 {%0,%1,%2,%3}, [%4];"
        : "=r"(r[0]), "=r"(r[1]), "=r"(r[2]), "=r"(r[3]) : "r"(addr));
}
__device__ __forceinline__ void mma16816h(float* d, const uint32_t* a, uint32_t b0, uint32_t b1) {
    asm volatile(
        "mma.sync.aligned.m16n8k16.row.col.f32.f16.f16.f32 "
        "{%0,%1,%2,%3}, {%4,%5,%6,%7}, {%8,%9}, {%0,%1,%2,%3};"
        : "+f"(d[0]), "+f"(d[1]), "+f"(d[2]), "+f"(d[3])
        : "r"(a[0]), "r"(a[1]), "r"(a[2]), "r"(a[3]), "r"(b0), "r"(b1));
}

// ---------------------------------------------------------------------------
// Prep kernels: fp32 -> fp16 conversions.
// ---------------------------------------------------------------------------
__global__ __launch_bounds__(256)
void prep_xh_kernel(const float* __restrict__ xs)
{
    size_t idx = (size_t)blockIdx.x * 256 + threadIdx.x;
    const float* s = xs + idx * 8;
    float4 a = *(const float4*)s;
    float4 b = *(const float4*)(s + 4);
    *(uint4*)(g_xh + idx * 16) = pack8h(a, b);
}

__global__ __launch_bounds__(256)
void prep_wih_kernel(const float* __restrict__ Wih)
{
    size_t idx = (size_t)blockIdx.x * 256 + threadIdx.x;
    const float* s = Wih + idx * 8;
    float4 a = *(const float4*)s;
    float4 b = *(const float4*)(s + 4);
    *(uint4*)(g_wih + idx * 16) = pack8h(a, b);
}

__global__ __launch_bounds__(256)
void prep_whh_kernel(const float* __restrict__ Whh)
{
    int idx = blockIdx.x * 256 + threadIdx.x;
    int kg = idx & 127;
    int r  = (idx >> 7) & 31;
    int j  = idx >> 12;

    int gate = r >> 3;
    int u    = 8 * j + (r & 7);
    const float* src = Whh + ((size_t)(gate * HH + u)) * HH + kg * 8;
    float4 a = *(const float4*)src;
    float4 b = *(const float4*)(src + 4);

    size_t off = ((size_t)(j * 32 + r) * HH + (size_t)kg * 8) * 2;
    *(uint4*)(g_whh + off) = pack8h(a, b);
}

__global__ __launch_bounds__(256)
void init_h_kernel(const float* __restrict__ h0)
{
    int idx = blockIdx.x * 256 + threadIdx.x;
    const float* src = h0 + (size_t)idx * 8;
    float4 a = *(const float4*)src;
    float4 b = *(const float4*)(src + 4);
    *(uint4*)(g_hb[0] + (size_t)idx * 16) = pack8h(a, b);
}

__global__ void reset_bar_kernel() { g_cnt = 0; }

// ---------------------------------------------------------------------------
// xproj GEMM on tensor cores (fp16): g_xproj = xs*Wih^T + bias.
// ---------------------------------------------------------------------------
__device__ __forceinline__ void xp_load_stage(uint32_t smb, int s, int c,
                                              int mbase, int nbase, int tid)
{
    uint32_t stg = smb + (uint32_t)s * XPSTG;
#pragma unroll
    for (int n = 0; n < 4; n++) {
        int i = tid + n * 256;
        int row = i >> 3;
        int col = i & 7;
        uint32_t d = (uint32_t)row * 144 + (uint32_t)col * 16;
        cpasync16(stg + XPA + d,
                  g_xh + ((size_t)(mbase + row) * INN + (size_t)c * 64 + col * 8) * 2);
        cpasync16(stg + XPB + d,
                  g_wih + ((size_t)(nbase + row) * INN + (size_t)c * 64 + col * 8) * 2);
    }
}

__global__ __launch_bounds__(256, 1)
void xprojmma_kernel(const float* __restrict__ bih, const float* __restrict__ bhh)
{
    extern __shared__ char sm[];
    uint32_t smb = smem_u32(sm);

    const int tid  = threadIdx.x;
    const int wid  = tid >> 5;
    const int lane = tid & 31;
    const int nbase = blockIdx.x * 128;
    const int mbase = blockIdx.y * 128;

    const int m0 = (wid & 1) * 64;
    const int n0 = (wid >> 1) * 32;

    const int mat = lane >> 3;
    const uint32_t arow = (uint32_t)((lane & 7) + ((mat & 1) << 3));
    const uint32_t acol = (uint32_t)(mat >> 1) * 16;
    const uint32_t brow = (uint32_t)((lane & 7) + ((mat >> 1) << 3));
    const uint32_t bcol = (uint32_t)(mat & 1) * 16;

    float acc[4][4][4];
#pragma unroll
    for (int im = 0; im < 4; im++)
#pragma unroll
        for (int in = 0; in < 4; in++)
#pragma unroll
            for (int k = 0; k < 4; k++) acc[im][in][k] = 0.0f;

#pragma unroll
    for (int c = 0; c < 3; c++) { xp_load_stage(smb, c, c, mbase, nbase, tid); CP_COMMIT(); }

    for (int c = 0; c < 8; c++) {
        CP_WAIT2();
        __syncthreads();
        if (c + 3 < 8) xp_load_stage(smb, (c + 3) & 3, c + 3, mbase, nbase, tid);
        CP_COMMIT();

        const uint32_t stg = smb + (uint32_t)(c & 3) * XPSTG;
#pragma unroll
        for (int ks = 0; ks < 4; ks++) {
            const uint32_t kb = (uint32_t)ks * 32;
            uint32_t a[4][4], b0[4], b1[4];
#pragma unroll
            for (int im = 0; im < 4; im++)
                ldm4(a[im], stg + XPA + (uint32_t)(m0 + im * 16 + arow) * 144 + acol + kb);
            ldm4(b0, stg + XPB + (uint32_t)(n0 + brow) * 144 + bcol + kb);
            ldm4(b1, stg + XPB + (uint32_t)(n0 + 16 + brow) * 144 + bcol + kb);
#pragma unroll
            for (int im = 0; im < 4; im++) {
                mma16816h(acc[im][0], a[im], b0[0], b0[1]);
                mma16816h(acc[im][1], a[im], b0[2], b0[3]);
                mma16816h(acc[im][2], a[im], b1[0], b1[1]);
                mma16816h(acc[im][3], a[im], b1[2], b1[3]);
            }
        }
    }

    const int crow  = lane >> 2;
    const int ccol2 = (lane & 3) * 2;
#pragma unroll
    for (int in = 0; in < 4; in++) {
        const int gcol = nbase + n0 + in * 8 + ccol2;
        float bx = bih[gcol]     + bhh[gcol];
        float by = bih[gcol + 1] + bhh[gcol + 1];
#pragma unroll
        for (int im = 0; im < 4; im++) {
            const int r0 = mbase + m0 + im * 16 + crow;
            float2 v0 = make_float2(acc[im][in][0] + bx, acc[im][in][1] + by);
            float2 v1 = make_float2(acc[im][in][2] + bx, acc[im][in][3] + by);
            *(float2*)(g_xproj + (size_t)r0 * G4 + gcol)       = v0;
            *(float2*)(g_xproj + (size_t)(r0 + 8) * G4 + gcol) = v1;
        }
    }
}

// ---------------------------------------------------------------------------
// Persistent LSTM kernel: 128 CTAs x 256 threads, all co-resident.
// W_hh (fp16) resident in SMEM; h (fp16 ping-pong) streams via 4-stage
// K=128 chunks; R9 red+poll grid barrier.
// ---------------------------------------------------------------------------
__device__ __forceinline__ void load_h_chunk(uint32_t smb, int s, int c, int tid,
                                             const unsigned char* hbase)
{
    uint32_t stg = smb + SM_H + (uint32_t)s * HSTG;
#pragma unroll
    for (int n = 0; n < 4; n++) {
        int i = tid + n * 256;            // 0..1023 (16B segs)
        int row = i >> 4;                 // batch 0..63
        int col = i & 15;                 // 16B col within 256B
        uint32_t d = (uint32_t)row * HPITCH + (uint32_t)col * 16;
        size_t sg = (size_t)row * 2048 + (size_t)c * 256 + (size_t)col * 16;
        cpasync16(stg + d, hbase + sg);
    }
}

__global__ __launch_bounds__(256, 1)
void persist_kernel(const float* __restrict__ c0, float* __restrict__ out)
{
    extern __shared__ char sm[];
    uint32_t smb = smem_u32(sm);

    const int tid  = threadIdx.x;
    const int wid  = tid >> 5;
    const int lane = tid & 31;
    const int j    = blockIdx.x;
    const int n0   = j * 8;

    const int m0  = (wid & 1) * 16;
    const int bn0 = (wid >> 1) * 16;

    const int mat = lane >> 3;
    const uint32_t aW   = (uint32_t)(m0 + (lane & 7) + ((mat & 1) << 3)) * WPITCH
                        + (uint32_t)(mat >> 1) * 16;
    const uint32_t boff = (uint32_t)(bn0 + (lane & 7) + ((mat >> 1) << 3)) * HPITCH
                        + (uint32_t)(mat & 1) * 16;

    // ---- load W tile into persistent SMEM (once) ----
    {
        const unsigned char* wh = g_whh + (size_t)j * 65536;
#pragma unroll
        for (int n = 0; n < 16; n++) {
            int e = n * 256 + tid;
            uint32_t d = (uint32_t)(e >> 7) * WPITCH + (uint32_t)(e & 127) * 16;
            cpasync16(smb + SM_W + d, wh + (size_t)e * 16);
        }
        CP_COMMIT();
        CP_WAIT0();
    }

    const int eb  = tid >> 2;
    const int eup = (tid & 3) * 2;
    float2 creg = *(const float2*)(c0 + (size_t)eb * HH + n0 + eup);
    __syncthreads();

    float* gs = (float*)(sm + SM_H);          // gate exchange overlay (stage 0)
    const float* xpb = (const float*)(sm + SM_XP);

    for (int t = 0; t < TT; t++) {
        const unsigned char* hread = g_hb[t & 1];
        unsigned char* hwrite      = g_hb[(t & 1) ^ 1];

        // ---- prologue: chunks 0..2 (+ xproj tile in group 0) ----
        load_h_chunk(smb, 0, 0, tid, hread);
        {
#pragma unroll
            for (int n = 0; n < 2; n++) {
                int i = tid * 2 + n;
                int half = i & 1;
                int g = (i >> 1) & 3;
                int b = i >> 3;
                const float* src = g_xproj + ((size_t)t * BB + b) * G4
                                 + (size_t)g * HH + n0 + half * 4;
                cpasync16(smb + SM_XP + (uint32_t)b * 128 + (uint32_t)g * 32
                          + (uint32_t)half * 16, src);
            }
        }
        CP_COMMIT();
        load_h_chunk(smb, 1, 1, tid, hread);
        CP_COMMIT();
        load_h_chunk(smb, 2, 2, tid, hread);
        CP_COMMIT();

        float acc[2][4];
#pragma unroll
        for (int i = 0; i < 2; i++)
#pragma unroll
            for (int k = 0; k < 4; k++) acc[i][k] = 0.0f;

        // ---- 8 K-chunks of 128, 4-stage pipeline ----
        for (int c = 0; c < NCHUNK; c++) {
            CP_WAIT2();
            __syncthreads();
            if (c + 3 < NCHUNK) load_h_chunk(smb, (c + 3) & 3, c + 3, tid, hread);
            CP_COMMIT();

            const uint32_t stg = smb + SM_H + (uint32_t)(c & 3) * HSTG;
            const uint32_t wcol = (uint32_t)c * 256;
#pragma unroll
            for (int ks = 0; ks < 8; ks++) {
                const uint32_t kb = (uint32_t)ks * 32;
                uint32_t ah[4], bh[4];
                ldm4(ah, smb + SM_W + aW + wcol + kb);
                ldm4(bh, stg + boff + kb);
                mma16816h(acc[0], ah, bh[0], bh[1]);
                mma16816h(acc[1], ah, bh[2], bh[3]);
            }
        }
        __syncthreads();

        // ---- gate exchange: fragments -> gs[32][68] ----
        {
            const int row0 = m0 + (lane >> 2);
            const int col0 = bn0 + (lane & 3) * 2;
            gs[row0 * 68 + col0]           = acc[0][0];
            gs[row0 * 68 + col0 + 1]       = acc[0][1];
            gs[(row0 + 8) * 68 + col0]     = acc[0][2];
            gs[(row0 + 8) * 68 + col0 + 1] = acc[0][3];
            gs[row0 * 68 + col0 + 8]       = acc[1][0];
            gs[row0 * 68 + col0 + 9]       = acc[1][1];
            gs[(row0 + 8) * 68 + col0 + 8] = acc[1][2];
            gs[(row0 + 8) * 68 + col0 + 9] = acc[1][3];
        }
        __syncthreads();

        // ---- fused epilogue (fast-math): (b, 2 units) per thread ----
        {
            float hv0, hv1;
            {
                const int u = eup;
                float gi = gs[(u)      * 68 + eb] + xpb[eb * 32 + 0 * 8 + u];
                float gf = gs[(8 + u)  * 68 + eb] + xpb[eb * 32 + 1 * 8 + u];
                float gg = gs[(16 + u) * 68 + eb] + xpb[eb * 32 + 2 * 8 + u];
                float go = gs[(24 + u) * 68 + eb] + xpb[eb * 32 + 3 * 8 + u];
                float ii = fsig(gi), ff = fsig(gf), gt = ftanh(gg), oo = fsig(go);
                float cn = ff * creg.x + ii * gt;
                creg.x = cn;
                hv0 = oo * ftanh(cn);
            }
            {
                const int u = eup + 1;
                float gi = gs[(u)      * 68 + eb] + xpb[eb * 32 + 0 * 8 + u];
                float gf = gs[(8 + u)  * 68 + eb] + xpb[eb * 32 + 1 * 8 + u];
                float gg = gs[(16 + u) * 68 + eb] + xpb[eb * 32 + 2 * 8 + u];
                float go = gs[(24 + u) * 68 + eb] + xpb[eb * 32 + 3 * 8 + u];
                float ii = fsig(gi), ff = fsig(gf), gt = ftanh(gg), oo = fsig(go);
                float cn = ff * creg.y + ii * gt;
                creg.y = cn;
                hv1 = oo * ftanh(cn);
            }

            *(float2*)(out + ((size_t)t * BB + eb) * HH + n0 + eup) = make_float2(hv0, hv1);

            __half2 hp = __floats2half2_rn(hv0, hv1);
            *(uint32_t*)(hwrite + (size_t)eb * 2048 + (size_t)(n0 + eup) * 2)
                = *(uint32_t*)&hp;
        }
        __syncthreads();

        // ---- grid barrier: fire-and-forget red + acquire poll (tid 0 only) ----
        if (tid == 0) {
            __threadfence();
            asm volatile("red.global.gpu.add.u32 [%0], %1;"
                         :: "l"(&g_cnt), "r"(1u) : "memory");
            const unsigned target = (unsigned)((t + 1) * NCTAP);
            unsigned v;
            do {
                asm volatile("ld.acquire.gpu.global.u32 %0, [%1];"
                             : "=r"(v) : "l"(&g_cnt) : "memory");
            } while (v < target);
        }
        __syncthreads();
    }
}

// ---------------------------------------------------------------------------
// Launch
// ---------------------------------------------------------------------------
extern "C" void kernel_launch(void* const* d_in, const int* in_sizes, int n_in,
                              void* d_out, int out_size)
{
    const float* xs  = (const float*)d_in[0];   // [T,B,IN]
    const float* h0  = (const float*)d_in[1];   // [B,H]
    const float* c0  = (const float*)d_in[2];   // [B,H]
    const float* Wih = (const float*)d_in[3];   // [4H,IN]
    const float* Whh = (const float*)d_in[4];   // [4H,H]
    const float* bih = (const float*)d_in[5];   // [4H]
    const float* bhh = (const float*)d_in[6];   // [4H]
    float* out = (float*)d_out;                 // [T,B,H]

    (void)in_sizes; (void)n_in; (void)out_size;

    cudaFuncSetAttribute(persist_kernel,  cudaFuncAttributeMaxDynamicSharedMemorySize, SMEM_REQ);
    cudaFuncSetAttribute(xprojmma_kernel, cudaFuncAttributeMaxDynamicSharedMemorySize, XP_SMEM);

    prep_xh_kernel<<<8192, 256>>>(xs);
    prep_wih_kernel<<<1024, 256>>>(Wih);
    prep_whh_kernel<<<2048, 256>>>(Whh);
    init_h_kernel<<<32, 256>>>(h0);
    reset_bar_kernel<<<1, 1>>>();

    xprojmma_kernel<<<dim3(32, 256), 256, XP_SMEM>>>(bih, bhh);

    persist_kernel<<<NCTAP, 256, SMEM_REQ>>>(c0, out);
}